// round 1
// baseline (speedup 1.0000x reference)
#include <cuda_runtime.h>

#define EPS 1e-5f

#define B   32
#define C   256
#define CCH 64      // CC
#define HS  64
#define PS  4096    // 64*64
#define PT  196     // 14*14

// ---------------- scratch (device globals: no allocation allowed) ----------------
__device__ float g_t   [B * CCH * PT];            // normalized template features
__device__ float g_tk  [B * CCH * 49];            // 7x7 depthwise kernels
__device__ float g_tg  [B * CCH];                 // template global means
__device__ float g_z   [(size_t)B * CCH * PS];    // raw search conv1x1 output
__device__ float g_corr[(size_t)B * CCH * PS];    // global + local correlation
__device__ float g_y   [(size_t)B * CCH * PS];    // raw conv3x3 output
__device__ float g_ab_s[B * CCH * 2];             // GN affine (alpha,beta) search
__device__ float g_ab_p[B * CCH * 2];             // GN affine (alpha,beta) post
__device__ float g_wT  [CCH * 9 * CCH];           // w_p1 transposed: [cin][k][co]

// =============================================================================
// K1: template branch: conv1x1 (256->64) + GroupNorm(32 groups) + ReLU
// one block per batch sample; 8cc x 7px register tile per thread
// =============================================================================
__global__ __launch_bounds__(256) void k_template(
    const float* __restrict__ tf, const float* __restrict__ w_t,
    const float* __restrict__ gnw, const float* __restrict__ gnb)
{
    __shared__ __align__(16) float smem[32 * 224 + 32 * 68]; // xs[32][224] + ws[32][68]
    float* xs = smem;
    float* ws = smem + 32 * 224;
    __shared__ float gm[32], grs[32];

    int b = blockIdx.x, t = threadIdx.x;
    int ccg = t >> 5;       // 0..7  (owns cc = ccg*8 .. +7)
    int pt  = t & 31;       // 0..31 (owns p = pt + 32*j)

    float acc[8][7];
#pragma unroll
    for (int i = 0; i < 8; i++)
#pragma unroll
        for (int j = 0; j < 7; j++) acc[i][j] = 0.f;

    for (int c0 = 0; c0 < C; c0 += 32) {
        for (int q = t; q < 32 * 224; q += 256) {
            int j = q / 224, p = q - j * 224;
            xs[q] = (p < PT) ? tf[(size_t)(b * C + c0 + j) * PT + p] : 0.f;
        }
        for (int q = t; q < 2048; q += 256) {
            int cc = q >> 5, j = q & 31;
            ws[j * 68 + cc] = w_t[cc * C + c0 + j];
        }
        __syncthreads();
#pragma unroll 4
        for (int j = 0; j < 32; j++) {
            float4 wa = *(const float4*)&ws[j * 68 + ccg * 8];
            float4 wb = *(const float4*)&ws[j * 68 + ccg * 8 + 4];
            float wv[8] = {wa.x, wa.y, wa.z, wa.w, wb.x, wb.y, wb.z, wb.w};
            float xv[7];
#pragma unroll
            for (int p = 0; p < 7; p++) xv[p] = xs[j * 224 + pt + 32 * p];
#pragma unroll
            for (int i = 0; i < 8; i++)
#pragma unroll
                for (int p = 0; p < 7; p++) acc[i][p] += wv[i] * xv[p];
        }
        __syncthreads();
    }

    // GroupNorm stats: group g = channels {2g, 2g+1}, 392 values each
    float* red  = smem;          // [64][33]
    float* red2 = smem + 64*33;  // [64][33]
#pragma unroll
    for (int i = 0; i < 8; i++) {
        float s = 0.f, s2 = 0.f;
#pragma unroll
        for (int p = 0; p < 7; p++) {
            int pp = pt + 32 * p;
            if (pp < PT) { s += acc[i][p]; s2 += acc[i][p] * acc[i][p]; }
        }
        int cc = ccg * 8 + i;
        red[cc * 33 + pt] = s;
        red2[cc * 33 + pt] = s2;
    }
    __syncthreads();
    if (t < 32) {
        float s = 0.f, s2 = 0.f;
        for (int cc = 2 * t; cc < 2 * t + 2; cc++)
            for (int q = 0; q < 32; q++) { s += red[cc * 33 + q]; s2 += red2[cc * 33 + q]; }
        float m = s / 392.f, v = s2 / 392.f - m * m;
        gm[t]  = m;
        grs[t] = rsqrtf(v + EPS);
    }
    __syncthreads();
#pragma unroll
    for (int i = 0; i < 8; i++) {
        int cc = ccg * 8 + i, g = cc >> 1;
        float a  = grs[g] * gnw[cc];
        float bb = gnb[cc] - gm[g] * a;
#pragma unroll
        for (int p = 0; p < 7; p++) {
            int pp = pt + 32 * p;
            if (pp < PT)
                g_t[(b * CCH + cc) * PT + pp] = fmaxf(acc[i][p] * a + bb, 0.f);
        }
    }
}

// =============================================================================
// K2: pooling: t_global (mean over 14x14), t_kernel (exact 2x2 mean -> 7x7)
// =============================================================================
__global__ __launch_bounds__(64) void k_pool()
{
    int cc = blockIdx.x, b = blockIdx.y, t = threadIdx.x;
    __shared__ float sp[64];
    const float* tp = g_t + (b * CCH + cc) * PT;
    float v = 0.f;
    if (t < 49) {
        int ky = t / 7, kx = t - 7 * (t / 7);
        const float* r0 = tp + (2 * ky) * 14 + 2 * kx;
        v = 0.25f * (r0[0] + r0[1] + r0[14] + r0[15]);
        g_tk[(b * CCH + cc) * 49 + t] = v;
    }
    sp[t] = v;
    __syncthreads();
    for (int o = 32; o > 0; o >>= 1) { if (t < o) sp[t] += sp[t + o]; __syncthreads(); }
    if (t == 0) g_tg[b * CCH + cc] = sp[0] * (1.f / 49.f);  // mean of all 196
}

// =============================================================================
// K3: search conv1x1 (256->64), raw output -> g_z.  8cc x 8px register tile.
// grid (32 px-tiles, 32 b), 128 threads
// =============================================================================
__global__ __launch_bounds__(128) void k_search(
    const float* __restrict__ sf, const float* __restrict__ w_s)
{
    __shared__ __align__(16) float xs[32 * 128];
    __shared__ __align__(16) float ws[32 * 68];
    int b = blockIdx.y, px0 = blockIdx.x * 128;
    int t = threadIdx.x;
    int ccg = t >> 4;  // 0..7
    int pxg = t & 15;  // 0..15, owns px = px0 + pxg + 16*j

    float acc[8][8];
#pragma unroll
    for (int i = 0; i < 8; i++)
#pragma unroll
        for (int j = 0; j < 8; j++) acc[i][j] = 0.f;

    for (int c0 = 0; c0 < C; c0 += 32) {
        for (int q = t; q < 1024; q += 128) {
            int j = q >> 5, col = q & 31;
            ((float4*)xs)[j * 32 + col] =
                *(const float4*)(sf + (size_t)(b * C + c0 + j) * PS + px0 + col * 4);
        }
        for (int q = t; q < 2048; q += 128) {
            int cc = q >> 5, j = q & 31;
            ws[j * 68 + cc] = w_s[cc * C + c0 + j];
        }
        __syncthreads();
#pragma unroll 4
        for (int j = 0; j < 32; j++) {
            float4 wa = *(const float4*)&ws[j * 68 + ccg * 8];
            float4 wb = *(const float4*)&ws[j * 68 + ccg * 8 + 4];
            float wv[8] = {wa.x, wa.y, wa.z, wa.w, wb.x, wb.y, wb.z, wb.w};
            float xv[8];
#pragma unroll
            for (int i = 0; i < 8; i++) xv[i] = xs[j * 128 + pxg + 16 * i];
#pragma unroll
            for (int ii = 0; ii < 8; ii++)
#pragma unroll
                for (int jj = 0; jj < 8; jj++) acc[ii][jj] += wv[ii] * xv[jj];
        }
        __syncthreads();
    }
#pragma unroll
    for (int ii = 0; ii < 8; ii++) {
        int cc = ccg * 8 + ii;
#pragma unroll
        for (int jj = 0; jj < 8; jj++)
            g_z[(size_t)(b * CCH + cc) * PS + px0 + pxg + 16 * jj] = acc[ii][jj];
    }
}

// =============================================================================
// K4: GroupNorm stats over (2 channels x 4096 px), deterministic tree reduce.
// Emits per-channel affine alpha/beta (normalize = alpha*x + beta).
// =============================================================================
__global__ __launch_bounds__(128) void k_stats(
    const float* __restrict__ src, const float* __restrict__ gnw,
    const float* __restrict__ gnb, float* __restrict__ ab)
{
    int g = blockIdx.x, b = blockIdx.y, t = threadIdx.x;
    const float* base = src + (size_t)(b * CCH + 2 * g) * PS;
    float s = 0.f, s2 = 0.f;
    for (int i = t; i < 2 * PS; i += 128) { float v = base[i]; s += v; s2 += v * v; }
    __shared__ float r1[128], r2[128];
    r1[t] = s; r2[t] = s2;
    __syncthreads();
    for (int o = 64; o > 0; o >>= 1) {
        if (t < o) { r1[t] += r1[t + o]; r2[t] += r2[t + o]; }
        __syncthreads();
    }
    if (t < 2) {
        int cc = 2 * g + t;
        float m = r1[0] / (2.f * PS);
        float v = r2[0] / (2.f * PS) - m * m;
        float a = rsqrtf(v + EPS) * gnw[cc];
        ab[(b * CCH + cc) * 2]     = a;
        ab[(b * CCH + cc) * 2 + 1] = gnb[cc] - m * a;
    }
}

// =============================================================================
// K5: depthwise 7x7 correlation + global correlation (folded into center tap).
// Normalizes z -> s = relu(alpha*z+beta) on the fly into a zero-padded halo.
// grid (64 cc, 32 b), 256 threads; 49 weights kept in registers.
// =============================================================================
__global__ __launch_bounds__(256) void k_dw()
{
    __shared__ float s[70 * 71];
    __shared__ float wsh[50];
    int cc = blockIdx.x, b = blockIdx.y, t = threadIdx.x;
    int bc = b * CCH + cc;
    size_t base = (size_t)bc * PS;
    float al = g_ab_s[bc * 2], be = g_ab_s[bc * 2 + 1];
    if (t < 49) wsh[t] = g_tk[bc * 49 + t];
    if (t == 49) wsh[49] = g_tg[bc];
    for (int i = t; i < 70 * 71; i += 256) s[i] = 0.f;
    __syncthreads();
    for (int i = t; i < PS; i += 256) {
        int yy = i >> 6, xx = i & 63;
        s[(yy + 3) * 71 + xx + 3] = fmaxf(al * g_z[base + i] + be, 0.f);
    }
    __syncthreads();
    float wr[49];
#pragma unroll
    for (int k = 0; k < 49; k++) wr[k] = wsh[k];
    wr[24] += wsh[49];  // global corr == extra center tap
    for (int gi = t; gi < 1024; gi += 256) {
        int yy = gi >> 4, xb = (gi & 15) << 2;
        float a0 = 0.f, a1 = 0.f, a2 = 0.f, a3 = 0.f;
#pragma unroll
        for (int dy = 0; dy < 7; dy++) {
            const float* row = &s[(yy + dy) * 71 + xb];
            float v[10];
#pragma unroll
            for (int d = 0; d < 10; d++) v[d] = row[d];
#pragma unroll
            for (int dx = 0; dx < 7; dx++) {
                float ww = wr[dy * 7 + dx];
                a0 += ww * v[dx];     a1 += ww * v[dx + 1];
                a2 += ww * v[dx + 2]; a3 += ww * v[dx + 3];
            }
        }
        float4 r = {a0, a1, a2, a3};
        *(float4*)&g_corr[base + yy * 64 + xb] = r;
    }
}

// =============================================================================
// K6: weight transpose for conv3x3: w_p1[co][cin][k] -> g_wT[cin][k][co]
// =============================================================================
__global__ __launch_bounds__(256) void k_wtrans(const float* __restrict__ w1)
{
    int i = blockIdx.x * 256 + threadIdx.x;
    if (i < CCH * CCH * 9) {
        int co = i / 576;
        int rem = i - co * 576;
        int cin = rem / 9, k = rem - 9 * cin;
        g_wT[(cin * 9 + k) * CCH + co] = w1[i];
    }
}

// =============================================================================
// K7: conv3x3 (64->64), SAME padding, raw output -> g_y.
// 16x16 px tile per block, 8cin chunk staged with halo, 8co x 8px reg tile.
// grid (16 tiles, 32 b), 256 threads
// =============================================================================
__global__ __launch_bounds__(256) void k_conv3()
{
    __shared__ __align__(16) float hs[8][18 * 19];
    __shared__ __align__(16) float wsm[8][9][64];
    int tile = blockIdx.x, b = blockIdx.y;
    int y0 = (tile >> 2) * 16, x0 = (tile & 3) * 16;
    int t = threadIdx.x;
    int ccg = t >> 5;        // 0..7
    int tx  = t & 31;
    int pr0 = tx >> 4;       // 0..1: owns rows pr0 + 2*i
    int pc  = tx & 15;       // 0..15: column within tile

    float acc[8][8];
#pragma unroll
    for (int i = 0; i < 8; i++)
#pragma unroll
        for (int j = 0; j < 8; j++) acc[i][j] = 0.f;

    for (int c0 = 0; c0 < CCH; c0 += 8) {
        for (int q = t; q < 8 * 324; q += 256) {
            int j = q / 324, rc = q - j * 324;
            int r = rc / 18, c2 = rc - 18 * r;
            int gy = y0 - 1 + r, gx = x0 - 1 + c2;
            float v = 0.f;
            if (gy >= 0 && gy < HS && gx >= 0 && gx < HS)
                v = g_corr[(size_t)(b * CCH + c0 + j) * PS + gy * HS + gx];
            hs[j][r * 19 + c2] = v;
        }
        for (int q = t; q < 8 * 9 * 64; q += 256)
            ((float*)wsm)[q] = g_wT[c0 * 9 * 64 + q];
        __syncthreads();
#pragma unroll 1
        for (int j = 0; j < 8; j++) {
#pragma unroll
            for (int k = 0; k < 9; k++) {
                int ky = k / 3, kx = k - 3 * (k / 3);
                float4 wa = *(const float4*)&wsm[j][k][ccg * 8];
                float4 wb = *(const float4*)&wsm[j][k][ccg * 8 + 4];
                float wv[8] = {wa.x, wa.y, wa.z, wa.w, wb.x, wb.y, wb.z, wb.w};
                float xv[8];
#pragma unroll
                for (int i = 0; i < 8; i++)
                    xv[i] = hs[j][(pr0 + 2 * i + ky) * 19 + pc + kx];
#pragma unroll
                for (int ii = 0; ii < 8; ii++)
#pragma unroll
                    for (int i = 0; i < 8; i++) acc[ii][i] += wv[ii] * xv[i];
            }
        }
        __syncthreads();
    }
#pragma unroll
    for (int ii = 0; ii < 8; ii++) {
        int co = ccg * 8 + ii;
#pragma unroll
        for (int i = 0; i < 8; i++) {
            int py = y0 + pr0 + 2 * i, px = x0 + pc;
            g_y[(size_t)(b * CCH + co) * PS + py * HS + px] = acc[ii][i];
        }
    }
}

// =============================================================================
// K8: final: out = b2 + sum_cc w2[cc] * relu(alpha*y + beta)
// =============================================================================
__global__ __launch_bounds__(256) void k_final(
    const float* __restrict__ w2, const float* __restrict__ b2,
    float* __restrict__ out)
{
    __shared__ float swv[64], sa[64], sb[64];
    int b = blockIdx.y, p0 = blockIdx.x * 256, t = threadIdx.x;
    if (t < 64) {
        swv[t] = w2[t];
        sa[t] = g_ab_p[(b * CCH + t) * 2];
        sb[t] = g_ab_p[(b * CCH + t) * 2 + 1];
    }
    __syncthreads();
    int p = p0 + t;
    float o = b2[0];
#pragma unroll 4
    for (int cc = 0; cc < 64; cc++) {
        float v = g_y[(size_t)(b * CCH + cc) * PS + p];
        o += swv[cc] * fmaxf(sa[cc] * v + sb[cc], 0.f);
    }
    out[b * PS + p] = o;
}

// =============================================================================
extern "C" void kernel_launch(void* const* d_in, const int* in_sizes, int n_in,
                              void* d_out, int out_size)
{
    (void)in_sizes; (void)n_in; (void)out_size;
    const float* tf  = (const float*)d_in[0];   // template_feat
    const float* sf  = (const float*)d_in[1];   // search_feat
    const float* w_t = (const float*)d_in[2];
    const float* gtw = (const float*)d_in[3];
    const float* gtb = (const float*)d_in[4];
    const float* w_s = (const float*)d_in[5];
    const float* gsw = (const float*)d_in[6];
    const float* gsb = (const float*)d_in[7];
    const float* w1  = (const float*)d_in[8];   // w_p1
    const float* gpw = (const float*)d_in[9];
    const float* gpb = (const float*)d_in[10];
    const float* w2  = (const float*)d_in[11];  // w_p2
    const float* b2  = (const float*)d_in[12];  // b_p2
    float* out = (float*)d_out;

    float *pz, *py, *pabs, *pabp;
    cudaGetSymbolAddress((void**)&pz,   g_z);
    cudaGetSymbolAddress((void**)&py,   g_y);
    cudaGetSymbolAddress((void**)&pabs, g_ab_s);
    cudaGetSymbolAddress((void**)&pabp, g_ab_p);

    k_template<<<B, 256>>>(tf, w_t, gtw, gtb);
    k_pool<<<dim3(CCH, B), 64>>>();
    k_search<<<dim3(32, B), 128>>>(sf, w_s);
    k_stats<<<dim3(32, B), 128>>>(pz, gsw, gsb, pabs);
    k_dw<<<dim3(CCH, B), 256>>>();
    k_wtrans<<<(CCH * CCH * 9 + 255) / 256, 256>>>(w1);
    k_conv3<<<dim3(16, B), 256>>>();
    k_stats<<<dim3(32, B), 128>>>(py, gpw, gpb, pabp);
    k_final<<<dim3(16, B), 256>>>(w2, b2, out);
}